// round 15
// baseline (speedup 1.0000x reference)
#include <cuda_runtime.h>
#include <cuda_bf16.h>
#include <cuda_fp16.h>
#include <math.h>
#include <stdint.h>

// Problem constants
constexpr int CB  = 2;
constexpr int CS  = 2048;
constexpr int CD  = 1024;
constexpr int CH  = 16;
constexpr int CHD = 64;
constexpr int MT  = CB * CS;  // 4096

// Scratch (allocation-free rule: static __device__ arrays)
__device__ __align__(256) float  g_q[MT * CD];
__device__ __align__(256) float  g_k[MT * CD];
__device__ __align__(256) float  g_v[MT * CD];
__device__ __align__(256) __half g_vals_h[MT * CD];  // attention out (fp16)
__device__ __align__(256) __half g_qh[MT * CD];      // fp16 inputs (GEMM A)
__device__ __align__(256) __half g_kih[MT * CD];
__device__ __align__(256) __half g_vih[MT * CD];
__device__ __align__(256) uint32_t g_ww[4 * CD / 2 * CD];  // fp16 pair-words W
__device__ __align__(256) __half g_kh[MT * CD];      // fp16 K after rope+rms
__device__ __align__(256) __half g_qs[MT * CD];      // fp16 q*QS after rope+rms
__device__ __align__(256) uint32_t g_vw[MT / 2 * CD];  // V pair-interleaved

// ---------------------------------------------------------------------------
// Helpers
// ---------------------------------------------------------------------------
__device__ __forceinline__ uint32_t packh2(float lo, float hi) {
    __half2 h = __floats2half2_rn(lo, hi);
    return *(uint32_t*)&h;
}

__device__ __forceinline__ float ex2(float x) {
    float r;
    asm("ex2.approx.f32 %0, %1;" : "=f"(r) : "f"(x));
    return r;
}

__device__ __forceinline__ void mma_f16(float c[4], const uint32_t a[4],
                                        const uint32_t b[2]) {
    asm volatile(
        "mma.sync.aligned.m16n8k16.row.col.f32.f16.f16.f32 "
        "{%0,%1,%2,%3}, {%4,%5,%6,%7}, {%8,%9}, {%0,%1,%2,%3};"
        : "+f"(c[0]), "+f"(c[1]), "+f"(c[2]), "+f"(c[3])
        : "r"(a[0]), "r"(a[1]), "r"(a[2]), "r"(a[3]), "r"(b[0]), "r"(b[1]));
}

__device__ __forceinline__ uint32_t smem_u32(const void* p) {
    uint32_t a;
    asm("{ .reg .u64 t; cvta.to.shared.u64 t, %1; cvt.u32.u64 %0, t; }"
        : "=r"(a) : "l"(p));
    return a;
}

__device__ __forceinline__ void cp16(uint32_t dst, const void* src) {
    asm volatile("cp.async.cg.shared.global [%0], [%1], 16;"
                 :: "r"(dst), "l"(src) : "memory");
}
#define CP_COMMIT() asm volatile("cp.async.commit_group;" ::: "memory")
#define CP_WAIT1()  asm volatile("cp.async.wait_group 1;" ::: "memory")

// ---------------------------------------------------------------------------
// prep: activations -> fp16 row-major; weights -> fp16 k-pair-interleaved.
// blockIdx.y: 0..2 act, 3..6 W.
// ---------------------------------------------------------------------------
__global__ __launch_bounds__(256) void prep_cvt(
    const float* __restrict__ Q, const float* __restrict__ K,
    const float* __restrict__ V, const float* __restrict__ Wq,
    const float* __restrict__ Wk, const float* __restrict__ Wv,
    const float* __restrict__ Wo, __half* __restrict__ qh,
    __half* __restrict__ kih, __half* __restrict__ vih,
    uint32_t* __restrict__ ww) {
    const int y = blockIdx.y;
    const int i = blockIdx.x * 256 + threadIdx.x;
    if (y < 3) {
        const float* src = (y == 0) ? Q : (y == 1) ? K : V;
        __half* dst = (y == 0) ? qh : (y == 1) ? kih : vih;
        if (i >= MT * CD / 4) return;
        float4 v = ((const float4*)src)[i];
        uint32_t w[2];
        w[0] = packh2(v.x, v.y);
        w[1] = packh2(v.z, v.w);
        *(uint2*)&dst[(size_t)i * 4] = *(uint2*)w;
    } else {
        const int wsel = y - 3;
        const float* W = (wsel == 0) ? Wq : (wsel == 1) ? Wk : (wsel == 2) ? Wv : Wo;
        uint32_t* dst = ww + (size_t)wsel * (CD / 2) * CD;
        if (i >= CD * CD / 8) return;
        const int kp = i / (CD / 4);
        const int n  = (i % (CD / 4)) * 4;
        const float4 a = *(const float4*)&W[(size_t)(2 * kp) * CD + n];
        const float4 b = *(const float4*)&W[(size_t)(2 * kp + 1) * CD + n];
        uint32_t w[4];
        w[0] = packh2(a.x, b.x);
        w[1] = packh2(a.y, b.y);
        w[2] = packh2(a.z, b.z);
        w[3] = packh2(a.w, b.w);
        *(int4*)&dst[(size_t)kp * CD + n] = *(int4*)w;
    }
}

// ---------------------------------------------------------------------------
// pack_v: V fp32 [b][s][h][d] -> f16x2 pair-words [b][s/2][h][d]:
// word = (V[2r][d], V[2r+1][d]). Exactly the smem layout attention needs.
// ---------------------------------------------------------------------------
__global__ __launch_bounds__(256) void pack_v(const float* __restrict__ gv,
                                              uint32_t* __restrict__ vw) {
    const int i = blockIdx.x * 256 + threadIdx.x;   // 4-word group
    if (i >= MT / 2 * CD / 4) return;
    const int dseg = (i & 15) * 4;                  // d column (4 words)
    const int rem  = i >> 4;                        // (b*(CS/2)+r)*CH + h
    const int h  = rem & 15;
    const int br = rem >> 4;
    const int r  = br & (CS / 2 - 1);
    const int b  = br / (CS / 2);
    const size_t f0 = ((size_t)(b * CS + 2 * r) * CD) + h * CHD + dseg;
    const float4 a = *(const float4*)&gv[f0];
    const float4 c = *(const float4*)&gv[f0 + CD];
    uint32_t w[4];
    w[0] = packh2(a.x, c.x);
    w[1] = packh2(a.y, c.y);
    w[2] = packh2(a.z, c.z);
    w[3] = packh2(a.w, c.w);
    *(int4*)&vw[(size_t)rem * CHD + dseg] = *(int4*)w;
}

// ---------------------------------------------------------------------------
// fp16 tensor-core GEMM v8 (unchanged from R13/R14 best).
// ---------------------------------------------------------------------------
constexpr int BM = 128, BN = 128;
constexpr int APADW = 20;
constexpr int BPADW = 136;
constexpr int ABYTES = BM * APADW * 4;
constexpr int BBYTES = 16 * BPADW * 4;
constexpr int STAGEB = ABYTES + BBYTES;
constexpr int GEMM_SMEM8 = 3 * STAGEB;  // 56832

__global__ __launch_bounds__(128) void hgemm_v8(
    const __half* __restrict__ A0, const __half* __restrict__ A1,
    const __half* __restrict__ A2, const uint32_t* __restrict__ WW,
    int wbase, float* __restrict__ C0, float* __restrict__ C1,
    float* __restrict__ C2, int M, int N, int K) {
    extern __shared__ char smem[];
    const uint32_t sb = smem_u32(smem);

    const int z = blockIdx.z;
    const __half* A = (z == 0) ? A0 : (z == 1) ? A1 : A2;
    const uint32_t* Wp = WW + (size_t)(wbase + z) * (CD / 2) * CD;
    float* C = (z == 0) ? C0 : (z == 1) ? C1 : C2;

    const int t    = threadIdx.x;
    const int lane = t & 31;
    const int warp = t >> 5;
    const int wm   = warp & 1;
    const int wn   = warp >> 1;
    const int gid  = lane >> 2;
    const int tg   = lane & 3;

    const int m0b = blockIdx.y * BM;
    const int n0b = blockIdx.x * BN;

    const int NC = K / 32;

    float c[4][8][4];
#pragma unroll
    for (int mt = 0; mt < 4; ++mt)
#pragma unroll
        for (int nt = 0; nt < 8; ++nt)
#pragma unroll
            for (int i = 0; i < 4; ++i) c[mt][nt][i] = 0.f;

    auto issue = [&](int ck, int s) {
        const int kn = ck * 32;
        const uint32_t abase = sb + s * STAGEB;
        const uint32_t bbase = abase + ABYTES;
#pragma unroll
        for (int i = 0; i < 4; ++i) {
            const int ci = t + i * 128;
            const int ar = ci >> 2, as = ci & 3;
            cp16(abase + ar * (APADW * 4) + as * 16,
                 &A[(size_t)(m0b + ar) * K + kn + as * 8]);
            const int br = ci >> 5, bs = ci & 31;
            cp16(bbase + (br * BPADW + bs * 4) * 4,
                 &Wp[(size_t)(kn / 2 + br) * N + n0b + bs * 4]);
        }
        CP_COMMIT();
    };

    issue(0, 0);
    issue(1, 1);

    for (int ck = 0; ck < NC; ++ck) {
        CP_WAIT1();
        __syncthreads();
        if (ck + 2 < NC) issue(ck + 2, (ck + 2) % 3);

        const int s = ck % 3;
        const uint32_t* As = (const uint32_t*)(smem + s * STAGEB);
        const uint32_t* Bs = (const uint32_t*)(smem + s * STAGEB + ABYTES);

#pragma unroll
        for (int ks = 0; ks < 2; ++ks) {
            uint32_t af[4][4], bf[8][2];
#pragma unroll
            for (int mt = 0; mt < 4; ++mt) {
                const int mm = wm * 64 + mt * 16 + gid;
                af[mt][0] = As[mm * APADW + ks * 8 + tg];
                af[mt][1] = As[(mm + 8) * APADW + ks * 8 + tg];
                af[mt][2] = As[mm * APADW + ks * 8 + tg + 4];
                af[mt][3] = As[(mm + 8) * APADW + ks * 8 + tg + 4];
            }
#pragma unroll
            for (int nt = 0; nt < 8; ++nt) {
                const int nn = wn * 64 + nt * 8 + gid;
                bf[nt][0] = Bs[(ks * 8 + tg) * BPADW + nn];
                bf[nt][1] = Bs[(ks * 8 + tg + 4) * BPADW + nn];
            }
#pragma unroll
            for (int mt = 0; mt < 4; ++mt)
#pragma unroll
                for (int nt = 0; nt < 8; ++nt) mma_f16(c[mt][nt], af[mt], bf[nt]);
        }
    }

#pragma unroll
    for (int mt = 0; mt < 4; ++mt) {
        const int r0 = m0b + wm * 64 + mt * 16 + gid;
#pragma unroll
        for (int nt = 0; nt < 8; ++nt) {
            const int cc = n0b + wn * 64 + nt * 8 + tg * 2;
            *(float2*)&C[(size_t)r0 * N + cc]       = make_float2(c[mt][nt][0], c[mt][nt][1]);
            *(float2*)&C[(size_t)(r0 + 8) * N + cc] = make_float2(c[mt][nt][2], c[mt][nt][3]);
        }
    }
}

// ---------------------------------------------------------------------------
// RoPE (bf16 cos/sin tables) + RMSNorm. blockIdx.y: 0=q (writes fp16 q*QS),
// 1=k (writes fp16).
// ---------------------------------------------------------------------------
__global__ __launch_bounds__(256) void rope_rms_kernel(
    const float* __restrict__ xq, const float* __restrict__ xk,
    __half* __restrict__ qs, __half* __restrict__ kh) {
    const bool isk = blockIdx.y;
    const float* x = isk ? xk : xq;
    const int gt   = blockIdx.x * blockDim.x + threadIdx.x;
    const int gw   = gt >> 5;
    const int lane = gt & 31;
    if (gw >= CB * CS * CH) return;

    const int sPos = (gw / CH) % CS;
    const float* p = x + (size_t)gw * CHD;

    const float x1 = p[lane];
    const float x2 = p[lane + 32];

    const float ex = (float)(2 * lane) * (1.0f / 64.0f);
    const float fr = powf(100000.0f, ex);
    const float g  = (float)sPos * (1.0f / fr);
    const float cc = __bfloat162float(__float2bfloat16(cosf(g)));
    const float sn = __bfloat162float(__float2bfloat16(sinf(g)));

    const float y1 = x1 * cc + x2 * sn;
    const float y2 = -x1 * sn + x2 * cc;

    float ss = y1 * y1 + y2 * y2;
#pragma unroll
    for (int o = 16; o > 0; o >>= 1) ss += __shfl_xor_sync(0xffffffffu, ss, o);

    const float rms = sqrtf(ss * (1.0f / 64.0f) + 1e-9f);
    const float ir  = 1.0f / rms;
    const float o1 = y1 * ir, o2 = y2 * ir;
    if (isk) {
        __half* ph = kh + (size_t)gw * CHD;
        ph[lane]      = __float2half_rn(o1);
        ph[lane + 32] = __float2half_rn(o2);
    } else {
        // fold 0.125*log2(e) so attention scores land in the log2 domain
        const float QS = 0.125f * 1.4426950408889634f;
        __half* ph = qs + (size_t)gw * CHD;
        ph[lane]      = __float2half_rn(o1 * QS);
        ph[lane + 32] = __float2half_rn(o2 * QS);
    }
}

// ---------------------------------------------------------------------------
// Causal flash attention, fp16 m16n8k16, no online max (|logit|<=8 bound),
// fully async KV fill: K fp16 + V pre-packed pair-words, both via cp.async,
// 3-stage pipeline, one barrier per tile.
// ---------------------------------------------------------------------------
__global__ __launch_bounds__(256, 2) void flash_attn_f16(
    const __half* __restrict__ qs, const __half* __restrict__ kh,
    const uint32_t* __restrict__ vw, __half* __restrict__ o) {
    __shared__ uint32_t Kw[3][32][36];
    __shared__ uint32_t Vw[3][16][72];

    const int t    = threadIdx.x;
    const int lane = t & 31;
    const int warp = t >> 5;
    const int gid  = lane >> 2;
    const int tg   = lane & 3;

    const int q0 = (gridDim.x - 1 - blockIdx.x) * 128;
    const int bh = blockIdx.y;
    const int b = bh >> 4, h = bh & 15;
    const size_t base  = ((size_t)b * CS * CH + h) * CHD;           // halves
    const size_t vbase = ((size_t)b * (CS / 2) * CH + h) * CHD;     // words
    const int rs = CH * CHD;  // 1024

    const int qrow0 = q0 + warp * 16 + gid;
    const int qrow1 = qrow0 + 8;

    const int kr_ = t >> 3;        // K row 0..31
    const int kw_ = (t & 7) * 4;   // K word seg
    const int vr_ = t >> 4;        // V pair-row 0..15
    const int vw4 = (t & 15) * 4;  // V word seg

    // Q a-fragments: plain fp16 word loads (scale pre-folded in rope)
    uint32_t qa[4][4];
#pragma unroll
    for (int ks = 0; ks < 4; ++ks) {
        qa[ks][0] = *(const uint32_t*)&qs[base + (size_t)qrow0 * rs + ks * 16 + 2 * tg];
        qa[ks][1] = *(const uint32_t*)&qs[base + (size_t)qrow1 * rs + ks * 16 + 2 * tg];
        qa[ks][2] = *(const uint32_t*)&qs[base + (size_t)qrow0 * rs + ks * 16 + 8 + 2 * tg];
        qa[ks][3] = *(const uint32_t*)&qs[base + (size_t)qrow1 * rs + ks * 16 + 8 + 2 * tg];
    }

    float oa[8][4];
#pragma unroll
    for (int dt = 0; dt < 8; ++dt)
#pragma unroll
        for (int i = 0; i < 4; ++i) oa[dt][i] = 0.f;

    float l0 = 0.f, l1 = 0.f;

    auto issue = [&](int kt, int s) {
        const int kv0 = kt << 5;
        cp16(smem_u32(&Kw[s][kr_][kw_]),
             &kh[base + (size_t)(kv0 + kr_) * rs + kw_ * 2]);
        cp16(smem_u32(&Vw[s][vr_][vw4]),
             &vw[vbase + (size_t)((kv0 >> 1) + vr_) * rs + vw4]);
        CP_COMMIT();
    };

    const int nkt = (q0 >> 5) + 4;
    issue(0, 0);
    if (nkt > 1) issue(1, 1);

    for (int kt = 0; kt < nkt; ++kt) {
        CP_WAIT1();
        __syncthreads();
        if (kt + 2 < nkt) issue(kt + 2, (kt + 2) % 3);

        const int s = kt % 3;
        const int kv0 = kt << 5;

        // ---- scores (log2 domain) ----
        float sc[4][4];
#pragma unroll
        for (int nt = 0; nt < 4; ++nt)
#pragma unroll
            for (int i = 0; i < 4; ++i) sc[nt][i] = 0.f;

#pragma unroll
        for (int ks = 0; ks < 4; ++ks) {
#pragma unroll
            for (int nt = 0; nt < 4; ++nt) {
                uint32_t bb[2];
                bb[0] = Kw[s][nt * 8 + gid][ks * 8 + tg];
                bb[1] = Kw[s][nt * 8 + gid][ks * 8 + tg + 4];
                mma_f16(sc[nt], qa[ks], bb);
            }
        }

        // ---- causal mask ----
        const bool needmask = (kv0 + 31 > qrow0);
        if (needmask) {
#pragma unroll
            for (int nt = 0; nt < 4; ++nt) {
                const int c0 = kv0 + nt * 8 + 2 * tg;
                const int c1 = c0 + 1;
                if (c0 > qrow0) sc[nt][0] = -1e9f;
                if (c1 > qrow0) sc[nt][1] = -1e9f;
                if (c0 > qrow1) sc[nt][2] = -1e9f;
                if (c1 > qrow1) sc[nt][3] = -1e9f;
            }
        }

        // ---- p = exp2(sc); accumulate row sums ----
        float pf[4][4];
        float s0 = 0.f, s1 = 0.f;
#pragma unroll
        for (int nt = 0; nt < 4; ++nt) {
            pf[nt][0] = ex2(sc[nt][0]);
            pf[nt][1] = ex2(sc[nt][1]);
            pf[nt][2] = ex2(sc[nt][2]);
            pf[nt][3] = ex2(sc[nt][3]);
            s0 += pf[nt][0] + pf[nt][1];
            s1 += pf[nt][2] + pf[nt][3];
        }
        l0 += s0;
        l1 += s1;

        // ---- P a-fragments: direct pack (fp16 FA identity) ----
        uint32_t pa[2][4];
#pragma unroll
        for (int hh = 0; hh < 2; ++hh) {
            pa[hh][0] = packh2(pf[2 * hh][0], pf[2 * hh][1]);
            pa[hh][1] = packh2(pf[2 * hh][2], pf[2 * hh][3]);
            pa[hh][2] = packh2(pf[2 * hh + 1][0], pf[2 * hh + 1][1]);
            pa[hh][3] = packh2(pf[2 * hh + 1][2], pf[2 * hh + 1][3]);
        }

        // ---- PV ----
#pragma unroll
        for (int ks2 = 0; ks2 < 2; ++ks2) {
#pragma unroll
            for (int dt = 0; dt < 8; ++dt) {
                uint32_t bb[2];
                bb[0] = Vw[s][ks2 * 8 + tg][dt * 8 + gid];
                bb[1] = Vw[s][ks2 * 8 + tg + 4][dt * 8 + gid];
                mma_f16(oa[dt], pa[ks2], bb);
            }
        }
    }

    // ---- row-sum reduction + normalize + fp16 store ----
    l0 += __shfl_xor_sync(0xffffffffu, l0, 1);
    l0 += __shfl_xor_sync(0xffffffffu, l0, 2);
    l1 += __shfl_xor_sync(0xffffffffu, l1, 1);
    l1 += __shfl_xor_sync(0xffffffffu, l1, 2);
    const float il0 = 1.0f / l0;
    const float il1 = 1.0f / l1;
#pragma unroll
    for (int dt = 0; dt < 8; ++dt) {
        const int cc = dt * 8 + 2 * tg;
        *(uint32_t*)&o[base + (size_t)qrow0 * rs + cc] =
            packh2(oa[dt][0] * il0, oa[dt][1] * il0);
        *(uint32_t*)&o[base + (size_t)qrow1 * rs + cc] =
            packh2(oa[dt][2] * il1, oa[dt][3] * il1);
    }
}

// ---------------------------------------------------------------------------
// Launch
// ---------------------------------------------------------------------------
extern "C" void kernel_launch(void* const* d_in, const int* in_sizes, int n_in,
                              void* d_out, int out_size) {
    (void)in_sizes; (void)n_in; (void)out_size;
    const float* Q  = (const float*)d_in[0];
    const float* K  = (const float*)d_in[1];
    const float* V  = (const float*)d_in[2];
    const float* Wq = (const float*)d_in[4];
    const float* Wk = (const float*)d_in[5];
    const float* Wv = (const float*)d_in[6];
    const float* Wo = (const float*)d_in[7];
    float* out = (float*)d_out;

    float *gq, *gk, *gv;
    __half *gvals_h, *qh, *kih, *vih, *kh, *qsh;
    uint32_t *ww, *vwp;
    cudaGetSymbolAddress((void**)&gq, g_q);
    cudaGetSymbolAddress((void**)&gk, g_k);
    cudaGetSymbolAddress((void**)&gv, g_v);
    cudaGetSymbolAddress((void**)&gvals_h, g_vals_h);
    cudaGetSymbolAddress((void**)&qh, g_qh);
    cudaGetSymbolAddress((void**)&kih, g_kih);
    cudaGetSymbolAddress((void**)&vih, g_vih);
    cudaGetSymbolAddress((void**)&ww, g_ww);
    cudaGetSymbolAddress((void**)&kh, g_kh);
    cudaGetSymbolAddress((void**)&qsh, g_qs);
    cudaGetSymbolAddress((void**)&vwp, g_vw);

    cudaFuncSetAttribute(hgemm_v8, cudaFuncAttributeMaxDynamicSharedMemorySize,
                         GEMM_SMEM8);

    const int M = MT;  // 4096

    // 0) pre-convert inputs + weights to fp16
    dim3 pgrid(MT * CD / 4 / 256, 7);
    prep_cvt<<<pgrid, 256>>>(Q, K, V, Wq, Wk, Wv, Wo, qh, kih, vih, ww);

    // 1) QKV projections
    dim3 ggrid3(CD / BN, M / BM, 3);
    hgemm_v8<<<ggrid3, 128, GEMM_SMEM8>>>(qh, kih, vih, ww, 0, gq, gk, gv, M,
                                          CD, CD);

    // 2) rope+rms (q -> fp16*QS, k -> fp16) and V pair-pack
    const int nwarps = CB * CS * CH;
    dim3 rgrid(nwarps / 8, 2);
    rope_rms_kernel<<<rgrid, 256>>>(gq, gk, qsh, kh);
    pack_v<<<MT / 2 * CD / 4 / 256, 256>>>(gv, vwp);

    // 3) attention (async fills; writes fp16)
    dim3 agrid(CS / 128, CB * CH);
    flash_attn_f16<<<agrid, 256>>>(qsh, kh, vwp, gvals_h);

    // 4) output projection
    dim3 ggrid1(CD / BN, M / BM, 1);
    hgemm_v8<<<ggrid1, 128, GEMM_SMEM8>>>(gvals_h, nullptr, nullptr, ww, 3,
                                          out, nullptr, nullptr, M, CD, CD);
}

// round 16
// speedup vs baseline: 1.1117x; 1.1117x over previous
#include <cuda_runtime.h>
#include <cuda_bf16.h>
#include <cuda_fp16.h>
#include <math.h>
#include <stdint.h>

// Problem constants
constexpr int CB  = 2;
constexpr int CS  = 2048;
constexpr int CD  = 1024;
constexpr int CH  = 16;
constexpr int CHD = 64;
constexpr int MT  = CB * CS;  // 4096

// Scratch (allocation-free rule: static __device__ arrays)
__device__ __align__(256) float  g_v[MT * CD];       // V projection (fp32)
__device__ __align__(256) __half g_vals_h[MT * CD];  // attention out (fp16)
__device__ __align__(256) __half g_qh[MT * CD];      // fp16 inputs (GEMM A)
__device__ __align__(256) __half g_kih[MT * CD];
__device__ __align__(256) __half g_vih[MT * CD];
__device__ __align__(256) uint32_t g_ww[4 * CD / 2 * CD];  // fp16 pair-words W
__device__ __align__(256) __half g_kh[MT * CD];      // fp16 K (rope+rms)
__device__ __align__(256) __half g_qs[MT * CD];      // fp16 q*QS (rope+rms)
__device__ __align__(256) uint32_t g_vw[MT / 2 * CD];  // V pair-interleaved
__device__ __align__(256) __nv_bfloat16 g_ct[CS * 32];  // bf16 cos table
__device__ __align__(256) __nv_bfloat16 g_st[CS * 32];  // bf16 sin table

// ---------------------------------------------------------------------------
// Helpers
// ---------------------------------------------------------------------------
__device__ __forceinline__ uint32_t packh2(float lo, float hi) {
    __half2 h = __floats2half2_rn(lo, hi);
    return *(uint32_t*)&h;
}

__device__ __forceinline__ float ex2(float x) {
    float r;
    asm("ex2.approx.f32 %0, %1;" : "=f"(r) : "f"(x));
    return r;
}

__device__ __forceinline__ void mma_f16(float c[4], const uint32_t a[4],
                                        const uint32_t b[2]) {
    asm volatile(
        "mma.sync.aligned.m16n8k16.row.col.f32.f16.f16.f32 "
        "{%0,%1,%2,%3}, {%4,%5,%6,%7}, {%8,%9}, {%0,%1,%2,%3};"
        : "+f"(c[0]), "+f"(c[1]), "+f"(c[2]), "+f"(c[3])
        : "r"(a[0]), "r"(a[1]), "r"(a[2]), "r"(a[3]), "r"(b[0]), "r"(b[1]));
}

__device__ __forceinline__ uint32_t smem_u32(const void* p) {
    uint32_t a;
    asm("{ .reg .u64 t; cvta.to.shared.u64 t, %1; cvt.u32.u64 %0, t; }"
        : "=r"(a) : "l"(p));
    return a;
}

__device__ __forceinline__ void cp16(uint32_t dst, const void* src) {
    asm volatile("cp.async.cg.shared.global [%0], [%1], 16;"
                 :: "r"(dst), "l"(src) : "memory");
}
#define CP_COMMIT() asm volatile("cp.async.commit_group;" ::: "memory")
#define CP_WAIT1()  asm volatile("cp.async.wait_group 1;" ::: "memory")

// ---------------------------------------------------------------------------
// prep: activations -> fp16 row-major; weights -> fp16 k-pair-interleaved.
// blockIdx.y: 0..2 act, 3..6 W.
// ---------------------------------------------------------------------------
__global__ __launch_bounds__(256) void prep_cvt(
    const float* __restrict__ Q, const float* __restrict__ K,
    const float* __restrict__ V, const float* __restrict__ Wq,
    const float* __restrict__ Wk, const float* __restrict__ Wv,
    const float* __restrict__ Wo, __half* __restrict__ qh,
    __half* __restrict__ kih, __half* __restrict__ vih,
    uint32_t* __restrict__ ww) {
    const int y = blockIdx.y;
    const int i = blockIdx.x * 256 + threadIdx.x;
    if (y < 3) {
        const float* src = (y == 0) ? Q : (y == 1) ? K : V;
        __half* dst = (y == 0) ? qh : (y == 1) ? kih : vih;
        if (i >= MT * CD / 4) return;
        float4 v = ((const float4*)src)[i];
        uint32_t w[2];
        w[0] = packh2(v.x, v.y);
        w[1] = packh2(v.z, v.w);
        *(uint2*)&dst[(size_t)i * 4] = *(uint2*)w;
    } else {
        const int wsel = y - 3;
        const float* W = (wsel == 0) ? Wq : (wsel == 1) ? Wk : (wsel == 2) ? Wv : Wo;
        uint32_t* dst = ww + (size_t)wsel * (CD / 2) * CD;
        if (i >= CD * CD / 8) return;
        const int kp = i / (CD / 4);
        const int n  = (i % (CD / 4)) * 4;
        const float4 a = *(const float4*)&W[(size_t)(2 * kp) * CD + n];
        const float4 b = *(const float4*)&W[(size_t)(2 * kp + 1) * CD + n];
        uint32_t w[4];
        w[0] = packh2(a.x, b.x);
        w[1] = packh2(a.y, b.y);
        w[2] = packh2(a.z, b.z);
        w[3] = packh2(a.w, b.w);
        *(int4*)&dst[(size_t)kp * CD + n] = *(int4*)w;
    }
}

// ---------------------------------------------------------------------------
// prep_tables: bf16 cos/sin RoPE tables (matches reference rounding).
// ---------------------------------------------------------------------------
__global__ __launch_bounds__(256) void prep_tables(
    __nv_bfloat16* __restrict__ ct, __nv_bfloat16* __restrict__ st) {
    const int i = blockIdx.x * 256 + threadIdx.x;
    if (i >= CS * 32) return;
    const int s = i >> 5, d = i & 31;
    const float fr = powf(100000.0f, (float)(2 * d) * (1.0f / 64.0f));
    const float g  = (float)s * (1.0f / fr);
    ct[i] = __float2bfloat16(cosf(g));
    st[i] = __float2bfloat16(sinf(g));
}

// ---------------------------------------------------------------------------
// pack_v: V fp32 [b][s][h][d] -> f16x2 pair-words (V[2r][d],V[2r+1][d]).
// ---------------------------------------------------------------------------
__global__ __launch_bounds__(256) void pack_v(const float* __restrict__ gv,
                                              uint32_t* __restrict__ vw) {
    const int i = blockIdx.x * 256 + threadIdx.x;
    if (i >= MT / 2 * CD / 4) return;
    const int dseg = (i & 15) * 4;
    const int rem  = i >> 4;
    const int h  = rem & 15;
    const int br = rem >> 4;
    const int r  = br & (CS / 2 - 1);
    const int b  = br / (CS / 2);
    const size_t f0 = ((size_t)(b * CS + 2 * r) * CD) + h * CHD + dseg;
    const float4 a = *(const float4*)&gv[f0];
    const float4 c = *(const float4*)&gv[f0 + CD];
    uint32_t w[4];
    w[0] = packh2(a.x, c.x);
    w[1] = packh2(a.y, c.y);
    w[2] = packh2(a.z, c.z);
    w[3] = packh2(a.w, c.w);
    *(int4*)&vw[(size_t)rem * CHD + dseg] = *(int4*)w;
}

// ---------------------------------------------------------------------------
// fp16 tensor-core GEMM v9: m16n8k16, cp.async 3-stage, BK=32, 128 threads
// (4 warps, 64x64 warp tiles). Fused epilogues:
//   wbase==0: z=0 -> rope+rms -> qs (fp16, QS folded)
//             z=1 -> rope+rms -> kh (fp16)
//             z=2 -> plain fp32 -> CF2
//   wbase==3: plain fp32 -> CFo
// Warp n-range (64 cols) == one head; RMS = quad shfl reduction.
// ---------------------------------------------------------------------------
constexpr int BM = 128, BN = 128;
constexpr int APADW = 20;
constexpr int BPADW = 136;
constexpr int ABYTES = BM * APADW * 4;
constexpr int BBYTES = 16 * BPADW * 4;
constexpr int STAGEB = ABYTES + BBYTES;
constexpr int GEMM_SMEM9 = 3 * STAGEB;  // 56832

__global__ __launch_bounds__(128) void hgemm_v9(
    const __half* __restrict__ A0, const __half* __restrict__ A1,
    const __half* __restrict__ A2, const uint32_t* __restrict__ WW,
    int wbase, float* __restrict__ CF2, float* __restrict__ CFo,
    __half* __restrict__ qsd, __half* __restrict__ khd,
    const __nv_bfloat16* __restrict__ ct, const __nv_bfloat16* __restrict__ st,
    int M, int N, int K) {
    extern __shared__ char smem[];
    const uint32_t sb = smem_u32(smem);

    const int z = blockIdx.z;
    const __half* A = (z == 0) ? A0 : (z == 1) ? A1 : A2;
    const uint32_t* Wp = WW + (size_t)(wbase + z) * (CD / 2) * CD;
    const int emode = (wbase == 0) ? z : 3;

    const int t    = threadIdx.x;
    const int lane = t & 31;
    const int warp = t >> 5;
    const int wm   = warp & 1;
    const int wn   = warp >> 1;
    const int gid  = lane >> 2;
    const int tg   = lane & 3;

    const int m0b = blockIdx.y * BM;
    const int n0b = blockIdx.x * BN;

    const int NC = K / 32;

    float c[4][8][4];
#pragma unroll
    for (int mt = 0; mt < 4; ++mt)
#pragma unroll
        for (int nt = 0; nt < 8; ++nt)
#pragma unroll
            for (int i = 0; i < 4; ++i) c[mt][nt][i] = 0.f;

    auto issue = [&](int ck, int s) {
        const int kn = ck * 32;
        const uint32_t abase = sb + s * STAGEB;
        const uint32_t bbase = abase + ABYTES;
#pragma unroll
        for (int i = 0; i < 4; ++i) {
            const int ci = t + i * 128;
            const int ar = ci >> 2, as = ci & 3;
            cp16(abase + ar * (APADW * 4) + as * 16,
                 &A[(size_t)(m0b + ar) * K + kn + as * 8]);
            const int br = ci >> 5, bs = ci & 31;
            cp16(bbase + (br * BPADW + bs * 4) * 4,
                 &Wp[(size_t)(kn / 2 + br) * N + n0b + bs * 4]);
        }
        CP_COMMIT();
    };

    issue(0, 0);
    issue(1, 1);

    for (int ck = 0; ck < NC; ++ck) {
        CP_WAIT1();
        __syncthreads();
        if (ck + 2 < NC) issue(ck + 2, (ck + 2) % 3);

        const int s = ck % 3;
        const uint32_t* As = (const uint32_t*)(smem + s * STAGEB);
        const uint32_t* Bs = (const uint32_t*)(smem + s * STAGEB + ABYTES);

#pragma unroll
        for (int ks = 0; ks < 2; ++ks) {
            uint32_t af[4][4], bf[8][2];
#pragma unroll
            for (int mt = 0; mt < 4; ++mt) {
                const int mm = wm * 64 + mt * 16 + gid;
                af[mt][0] = As[mm * APADW + ks * 8 + tg];
                af[mt][1] = As[(mm + 8) * APADW + ks * 8 + tg];
                af[mt][2] = As[mm * APADW + ks * 8 + tg + 4];
                af[mt][3] = As[(mm + 8) * APADW + ks * 8 + tg + 4];
            }
#pragma unroll
            for (int nt = 0; nt < 8; ++nt) {
                const int nn = wn * 64 + nt * 8 + gid;
                bf[nt][0] = Bs[(ks * 8 + tg) * BPADW + nn];
                bf[nt][1] = Bs[(ks * 8 + tg + 4) * BPADW + nn];
            }
#pragma unroll
            for (int mt = 0; mt < 4; ++mt)
#pragma unroll
                for (int nt = 0; nt < 8; ++nt) mma_f16(c[mt][nt], af[mt], bf[nt]);
        }
    }

    if (emode >= 2) {
        // plain fp32 epilogue
        float* C = (emode == 2) ? CF2 : CFo;
#pragma unroll
        for (int mt = 0; mt < 4; ++mt) {
            const int r0 = m0b + wm * 64 + mt * 16 + gid;
#pragma unroll
            for (int nt = 0; nt < 8; ++nt) {
                const int cc = n0b + wn * 64 + nt * 8 + tg * 2;
                *(float2*)&C[(size_t)r0 * N + cc]       = make_float2(c[mt][nt][0], c[mt][nt][1]);
                *(float2*)&C[(size_t)(r0 + 8) * N + cc] = make_float2(c[mt][nt][2], c[mt][nt][3]);
            }
        }
    } else {
        // fused rope + rms epilogue; warp's 64 n-cols == one head
        const float scale =
            (emode == 0) ? (0.125f * 1.4426950408889634f) : 1.0f;
        __half* dst = (emode == 0) ? qsd : khd;
        const int head = blockIdx.x * 2 + wn;
#pragma unroll
        for (int mt = 0; mt < 4; ++mt) {
#pragma unroll
            for (int hf = 0; hf < 2; ++hf) {
                const int row = m0b + wm * 64 + mt * 16 + gid + hf * 8;
                const int sp  = row & (CS - 1);
                float y1[8], y2[8];
                float ss = 0.f;
#pragma unroll
                for (int nt = 0; nt < 4; ++nt) {
                    const int d = nt * 8 + tg * 2;
                    const uint32_t cw = *(const uint32_t*)&ct[sp * 32 + d];
                    const uint32_t sw = *(const uint32_t*)&st[sp * 32 + d];
                    const __nv_bfloat162 cb = *(const __nv_bfloat162*)&cw;
                    const __nv_bfloat162 sb2 = *(const __nv_bfloat162*)&sw;
                    const float c0 = __bfloat162float(cb.x);
                    const float c1 = __bfloat162float(cb.y);
                    const float s0 = __bfloat162float(sb2.x);
                    const float s1 = __bfloat162float(sb2.y);
                    const float x1a = c[mt][nt][hf * 2 + 0];
                    const float x1b = c[mt][nt][hf * 2 + 1];
                    const float x2a = c[mt][nt + 4][hf * 2 + 0];
                    const float x2b = c[mt][nt + 4][hf * 2 + 1];
                    y1[2 * nt + 0] = x1a * c0 + x2a * s0;
                    y2[2 * nt + 0] = -x1a * s0 + x2a * c0;
                    y1[2 * nt + 1] = x1b * c1 + x2b * s1;
                    y2[2 * nt + 1] = -x1b * s1 + x2b * c1;
                    ss += y1[2 * nt] * y1[2 * nt] + y2[2 * nt] * y2[2 * nt] +
                          y1[2 * nt + 1] * y1[2 * nt + 1] +
                          y2[2 * nt + 1] * y2[2 * nt + 1];
                }
                ss += __shfl_xor_sync(0xffffffffu, ss, 1);
                ss += __shfl_xor_sync(0xffffffffu, ss, 2);
                const float rms = sqrtf(ss * (1.0f / 64.0f) + 1e-9f);
                const float ir  = scale / rms;
                const size_t ob = (size_t)row * CD + head * CHD;
#pragma unroll
                for (int nt = 0; nt < 4; ++nt) {
                    const int d = nt * 8 + tg * 2;
                    *(uint32_t*)&dst[ob + d] =
                        packh2(y1[2 * nt] * ir, y1[2 * nt + 1] * ir);
                    *(uint32_t*)&dst[ob + d + 32] =
                        packh2(y2[2 * nt] * ir, y2[2 * nt + 1] * ir);
                }
            }
        }
    }
}

// ---------------------------------------------------------------------------
// Causal flash attention, fp16 m16n8k16, no online max (|logit|<=8 bound),
// fully async KV fill (K fp16 + V pre-packed), 3-stage pipeline.
// ---------------------------------------------------------------------------
__global__ __launch_bounds__(256, 2) void flash_attn_f16(
    const __half* __restrict__ qs, const __half* __restrict__ kh,
    const uint32_t* __restrict__ vw, __half* __restrict__ o) {
    __shared__ uint32_t Kw[3][32][36];
    __shared__ uint32_t Vw[3][16][72];

    const int t    = threadIdx.x;
    const int lane = t & 31;
    const int warp = t >> 5;
    const int gid  = lane >> 2;
    const int tg   = lane & 3;

    const int q0 = (gridDim.x - 1 - blockIdx.x) * 128;
    const int bh = blockIdx.y;
    const int b = bh >> 4, h = bh & 15;
    const size_t base  = ((size_t)b * CS * CH + h) * CHD;
    const size_t vbase = ((size_t)b * (CS / 2) * CH + h) * CHD;
    const int rs = CH * CHD;

    const int qrow0 = q0 + warp * 16 + gid;
    const int qrow1 = qrow0 + 8;

    const int kr_ = t >> 3;
    const int kw_ = (t & 7) * 4;
    const int vr_ = t >> 4;
    const int vw4 = (t & 15) * 4;

    uint32_t qa[4][4];
#pragma unroll
    for (int ks = 0; ks < 4; ++ks) {
        qa[ks][0] = *(const uint32_t*)&qs[base + (size_t)qrow0 * rs + ks * 16 + 2 * tg];
        qa[ks][1] = *(const uint32_t*)&qs[base + (size_t)qrow1 * rs + ks * 16 + 2 * tg];
        qa[ks][2] = *(const uint32_t*)&qs[base + (size_t)qrow0 * rs + ks * 16 + 8 + 2 * tg];
        qa[ks][3] = *(const uint32_t*)&qs[base + (size_t)qrow1 * rs + ks * 16 + 8 + 2 * tg];
    }

    float oa[8][4];
#pragma unroll
    for (int dt = 0; dt < 8; ++dt)
#pragma unroll
        for (int i = 0; i < 4; ++i) oa[dt][i] = 0.f;

    float l0 = 0.f, l1 = 0.f;

    auto issue = [&](int kt, int s) {
        const int kv0 = kt << 5;
        cp16(smem_u32(&Kw[s][kr_][kw_]),
             &kh[base + (size_t)(kv0 + kr_) * rs + kw_ * 2]);
        cp16(smem_u32(&Vw[s][vr_][vw4]),
             &vw[vbase + (size_t)((kv0 >> 1) + vr_) * rs + vw4]);
        CP_COMMIT();
    };

    const int nkt = (q0 >> 5) + 4;
    issue(0, 0);
    if (nkt > 1) issue(1, 1);

    for (int kt = 0; kt < nkt; ++kt) {
        CP_WAIT1();
        __syncthreads();
        if (kt + 2 < nkt) issue(kt + 2, (kt + 2) % 3);

        const int s = kt % 3;
        const int kv0 = kt << 5;

        float sc[4][4];
#pragma unroll
        for (int nt = 0; nt < 4; ++nt)
#pragma unroll
            for (int i = 0; i < 4; ++i) sc[nt][i] = 0.f;

#pragma unroll
        for (int ks = 0; ks < 4; ++ks) {
#pragma unroll
            for (int nt = 0; nt < 4; ++nt) {
                uint32_t bb[2];
                bb[0] = Kw[s][nt * 8 + gid][ks * 8 + tg];
                bb[1] = Kw[s][nt * 8 + gid][ks * 8 + tg + 4];
                mma_f16(sc[nt], qa[ks], bb);
            }
        }

        const bool needmask = (kv0 + 31 > qrow0);
        if (needmask) {
#pragma unroll
            for (int nt = 0; nt < 4; ++nt) {
                const int c0 = kv0 + nt * 8 + 2 * tg;
                const int c1 = c0 + 1;
                if (c0 > qrow0) sc[nt][0] = -1e9f;
                if (c1 > qrow0) sc[nt][1] = -1e9f;
                if (c0 > qrow1) sc[nt][2] = -1e9f;
                if (c1 > qrow1) sc[nt][3] = -1e9f;
            }
        }

        float pf[4][4];
        float s0 = 0.f, s1 = 0.f;
#pragma unroll
        for (int nt = 0; nt < 4; ++nt) {
            pf[nt][0] = ex2(sc[nt][0]);
            pf[nt][1] = ex2(sc[nt][1]);
            pf[nt][2] = ex2(sc[nt][2]);
            pf[nt][3] = ex2(sc[nt][3]);
            s0 += pf[nt][0] + pf[nt][1];
            s1 += pf[nt][2] + pf[nt][3];
        }
        l0 += s0;
        l1 += s1;

        uint32_t pa[2][4];
#pragma unroll
        for (int hh = 0; hh < 2; ++hh) {
            pa[hh][0] = packh2(pf[2 * hh][0], pf[2 * hh][1]);
            pa[hh][1] = packh2(pf[2 * hh][2], pf[2 * hh][3]);
            pa[hh][2] = packh2(pf[2 * hh + 1][0], pf[2 * hh + 1][1]);
            pa[hh][3] = packh2(pf[2 * hh + 1][2], pf[2 * hh + 1][3]);
        }

#pragma unroll
        for (int ks2 = 0; ks2 < 2; ++ks2) {
#pragma unroll
            for (int dt = 0; dt < 8; ++dt) {
                uint32_t bb[2];
                bb[0] = Vw[s][ks2 * 8 + tg][dt * 8 + gid];
                bb[1] = Vw[s][ks2 * 8 + tg + 4][dt * 8 + gid];
                mma_f16(oa[dt], pa[ks2], bb);
            }
        }
    }

    l0 += __shfl_xor_sync(0xffffffffu, l0, 1);
    l0 += __shfl_xor_sync(0xffffffffu, l0, 2);
    l1 += __shfl_xor_sync(0xffffffffu, l1, 1);
    l1 += __shfl_xor_sync(0xffffffffu, l1, 2);
    const float il0 = 1.0f / l0;
    const float il1 = 1.0f / l1;
#pragma unroll
    for (int dt = 0; dt < 8; ++dt) {
        const int cc = dt * 8 + 2 * tg;
        *(uint32_t*)&o[base + (size_t)qrow0 * rs + cc] =
            packh2(oa[dt][0] * il0, oa[dt][1] * il0);
        *(uint32_t*)&o[base + (size_t)qrow1 * rs + cc] =
            packh2(oa[dt][2] * il1, oa[dt][3] * il1);
    }
}

// ---------------------------------------------------------------------------
// Launch
// ---------------------------------------------------------------------------
extern "C" void kernel_launch(void* const* d_in, const int* in_sizes, int n_in,
                              void* d_out, int out_size) {
    (void)in_sizes; (void)n_in; (void)out_size;
    const float* Q  = (const float*)d_in[0];
    const float* K  = (const float*)d_in[1];
    const float* V  = (const float*)d_in[2];
    const float* Wq = (const float*)d_in[4];
    const float* Wk = (const float*)d_in[5];
    const float* Wv = (const float*)d_in[6];
    const float* Wo = (const float*)d_in[7];
    float* out = (float*)d_out;

    float* gv;
    __half *gvals_h, *qh, *kih, *vih, *kh, *qsh;
    uint32_t *ww, *vwp;
    __nv_bfloat16 *ct, *st;
    cudaGetSymbolAddress((void**)&gv, g_v);
    cudaGetSymbolAddress((void**)&gvals_h, g_vals_h);
    cudaGetSymbolAddress((void**)&qh, g_qh);
    cudaGetSymbolAddress((void**)&kih, g_kih);
    cudaGetSymbolAddress((void**)&vih, g_vih);
    cudaGetSymbolAddress((void**)&ww, g_ww);
    cudaGetSymbolAddress((void**)&kh, g_kh);
    cudaGetSymbolAddress((void**)&qsh, g_qs);
    cudaGetSymbolAddress((void**)&vwp, g_vw);
    cudaGetSymbolAddress((void**)&ct, g_ct);
    cudaGetSymbolAddress((void**)&st, g_st);

    cudaFuncSetAttribute(hgemm_v9, cudaFuncAttributeMaxDynamicSharedMemorySize,
                         GEMM_SMEM9);

    const int M = MT;  // 4096

    // 0) pre-convert inputs + weights to fp16; rope tables
    dim3 pgrid(MT * CD / 4 / 256, 7);
    prep_cvt<<<pgrid, 256>>>(Q, K, V, Wq, Wk, Wv, Wo, qh, kih, vih, ww);
    prep_tables<<<CS * 32 / 256, 256>>>(ct, st);

    // 1) QKV projections with fused rope+rms epilogues (q->qs, k->kh, v->gv)
    dim3 ggrid3(CD / BN, M / BM, 3);
    hgemm_v9<<<ggrid3, 128, GEMM_SMEM9>>>(qh, kih, vih, ww, 0, gv, nullptr,
                                          qsh, kh, ct, st, M, CD, CD);

    // 2) V pair-pack
    pack_v<<<MT / 2 * CD / 4 / 256, 256>>>(gv, vwp);

    // 3) attention (async fills; writes fp16)
    dim3 agrid(CS / 128, CB * CH);
    flash_attn_f16<<<agrid, 256>>>(qsh, kh, vwp, gvals_h);

    // 4) output projection (plain fp32 epilogue)
    dim3 ggrid1(CD / BN, M / BM, 1);
    hgemm_v9<<<ggrid1, 128, GEMM_SMEM9>>>(gvals_h, nullptr, nullptr, ww, 3,
                                          nullptr, out, nullptr, nullptr, ct,
                                          st, M, CD, CD);
}

// round 17
// speedup vs baseline: 1.1692x; 1.0518x over previous
#include <cuda_runtime.h>
#include <cuda_bf16.h>
#include <cuda_fp16.h>
#include <math.h>
#include <stdint.h>

// Problem constants
constexpr int CB  = 2;
constexpr int CS  = 2048;
constexpr int CD  = 1024;
constexpr int CH  = 16;
constexpr int CHD = 64;
constexpr int MT  = CB * CS;  // 4096

// Scratch (allocation-free rule: static __device__ arrays)
__device__ __align__(256) float  g_v[MT * CD];       // V projection (fp32)
__device__ __align__(256) __half g_vals_h[MT * CD];  // attention out (fp16)
__device__ __align__(256) __half g_qh[MT * CD];      // fp16 inputs (GEMM A)
__device__ __align__(256) __half g_kih[MT * CD];
__device__ __align__(256) __half g_vih[MT * CD];
__device__ __align__(256) uint32_t g_ww[4 * CD / 2 * CD];  // fp16 pair-words W
__device__ __align__(256) __half g_kh[MT * CD];      // fp16 K (rope+rms)
__device__ __align__(256) __half g_qs[MT * CD];      // fp16 q*QS (rope+rms)
__device__ __align__(256) uint32_t g_vt[MT / 2 * CD];   // V d-major pair words
__device__ __align__(256) __nv_bfloat16 g_ct[CS * 32];  // bf16 cos table
__device__ __align__(256) __nv_bfloat16 g_st[CS * 32];  // bf16 sin table

// ---------------------------------------------------------------------------
// Helpers
// ---------------------------------------------------------------------------
__device__ __forceinline__ uint32_t packh2(float lo, float hi) {
    __half2 h = __floats2half2_rn(lo, hi);
    return *(uint32_t*)&h;
}

__device__ __forceinline__ float ex2(float x) {
    float r;
    asm("ex2.approx.f32 %0, %1;" : "=f"(r) : "f"(x));
    return r;
}

__device__ __forceinline__ void mma_f16(float c[4], const uint32_t a[4],
                                        const uint32_t b0, const uint32_t b1) {
    asm volatile(
        "mma.sync.aligned.m16n8k16.row.col.f32.f16.f16.f32 "
        "{%0,%1,%2,%3}, {%4,%5,%6,%7}, {%8,%9}, {%0,%1,%2,%3};"
        : "+f"(c[0]), "+f"(c[1]), "+f"(c[2]), "+f"(c[3])
        : "r"(a[0]), "r"(a[1]), "r"(a[2]), "r"(a[3]), "r"(b0), "r"(b1));
}

__device__ __forceinline__ void ldsm4(uint32_t& r0, uint32_t& r1, uint32_t& r2,
                                      uint32_t& r3, uint32_t addr) {
    asm volatile(
        "ldmatrix.sync.aligned.m8n8.x4.shared.b16 {%0,%1,%2,%3}, [%4];"
        : "=r"(r0), "=r"(r1), "=r"(r2), "=r"(r3) : "r"(addr));
}

__device__ __forceinline__ uint32_t smem_u32(const void* p) {
    uint32_t a;
    asm("{ .reg .u64 t; cvta.to.shared.u64 t, %1; cvt.u32.u64 %0, t; }"
        : "=r"(a) : "l"(p));
    return a;
}

__device__ __forceinline__ void cp16(uint32_t dst, const void* src) {
    asm volatile("cp.async.cg.shared.global [%0], [%1], 16;"
                 :: "r"(dst), "l"(src) : "memory");
}
#define CP_COMMIT() asm volatile("cp.async.commit_group;" ::: "memory")
#define CP_WAIT1()  asm volatile("cp.async.wait_group 1;" ::: "memory")
#define CP_WAIT0()  asm volatile("cp.async.wait_group 0;" ::: "memory")

// ---------------------------------------------------------------------------
// prep: activations -> fp16 row-major; weights -> fp16 k-pair-interleaved.
// blockIdx.y: 0..2 act, 3..6 W.
// ---------------------------------------------------------------------------
__global__ __launch_bounds__(256) void prep_cvt(
    const float* __restrict__ Q, const float* __restrict__ K,
    const float* __restrict__ V, const float* __restrict__ Wq,
    const float* __restrict__ Wk, const float* __restrict__ Wv,
    const float* __restrict__ Wo, __half* __restrict__ qh,
    __half* __restrict__ kih, __half* __restrict__ vih,
    uint32_t* __restrict__ ww) {
    const int y = blockIdx.y;
    const int i = blockIdx.x * 256 + threadIdx.x;
    if (y < 3) {
        const float* src = (y == 0) ? Q : (y == 1) ? K : V;
        __half* dst = (y == 0) ? qh : (y == 1) ? kih : vih;
        if (i >= MT * CD / 4) return;
        float4 v = ((const float4*)src)[i];
        uint32_t w[2];
        w[0] = packh2(v.x, v.y);
        w[1] = packh2(v.z, v.w);
        *(uint2*)&dst[(size_t)i * 4] = *(uint2*)w;
    } else {
        const int wsel = y - 3;
        const float* W = (wsel == 0) ? Wq : (wsel == 1) ? Wk : (wsel == 2) ? Wv : Wo;
        uint32_t* dst = ww + (size_t)wsel * (CD / 2) * CD;
        if (i >= CD * CD / 8) return;
        const int kp = i / (CD / 4);
        const int n  = (i % (CD / 4)) * 4;
        const float4 a = *(const float4*)&W[(size_t)(2 * kp) * CD + n];
        const float4 b = *(const float4*)&W[(size_t)(2 * kp + 1) * CD + n];
        uint32_t w[4];
        w[0] = packh2(a.x, b.x);
        w[1] = packh2(a.y, b.y);
        w[2] = packh2(a.z, b.z);
        w[3] = packh2(a.w, b.w);
        *(int4*)&dst[(size_t)kp * CD + n] = *(int4*)w;
    }
}

// ---------------------------------------------------------------------------
// prep_tables: bf16 cos/sin RoPE tables (matches reference rounding).
// ---------------------------------------------------------------------------
__global__ __launch_bounds__(256) void prep_tables(
    __nv_bfloat16* __restrict__ ct, __nv_bfloat16* __restrict__ st) {
    const int i = blockIdx.x * 256 + threadIdx.x;
    if (i >= CS * 32) return;
    const int s = i >> 5, d = i & 31;
    const float fr = powf(100000.0f, (float)(2 * d) * (1.0f / 64.0f));
    const float g  = (float)s * (1.0f / fr);
    ct[i] = __float2bfloat16(cosf(g));
    st[i] = __float2bfloat16(sinf(g));
}

// ---------------------------------------------------------------------------
// pack_vt: V fp32 [b][s][h][d] -> d-major f16x2 pair-words
// vt[((b*CH+h)*64 + d) * (CS/2) + p] = (V[2p][d], V[2p+1][d]).
// Block: one (bh, 64-s x 64-d tile), smem transpose.
// ---------------------------------------------------------------------------
__global__ __launch_bounds__(256) void pack_vt(const float* __restrict__ gv,
                                               uint32_t* __restrict__ vt) {
    __shared__ float ts[64][68];
    const int bh = blockIdx.y;
    const int b = bh >> 4, h = bh & 15;
    const int s0 = blockIdx.x * 64;
    const int t = threadIdx.x;

    const int row = t >> 2;
    const int ds  = (t & 3) * 16;
    const size_t src = ((size_t)(b * CS + s0 + row) * CD) + h * CHD + ds;
#pragma unroll
    for (int i = 0; i < 4; ++i)
        *(float4*)&ts[row][ds + i * 4] = *(const float4*)&gv[src + i * 4];
    __syncthreads();

    const int d  = t >> 2;
    const int p0 = (t & 3) * 8;
    uint32_t w[8];
#pragma unroll
    for (int i = 0; i < 8; ++i)
        w[i] = packh2(ts[2 * (p0 + i)][d], ts[2 * (p0 + i) + 1][d]);
    const size_t dst = ((size_t)bh * 64 + d) * (CS / 2) + (s0 >> 1) + p0;
    *(int4*)&vt[dst]     = *(int4*)&w[0];
    *(int4*)&vt[dst + 4] = *(int4*)&w[4];
}

// ---------------------------------------------------------------------------
// fp16 tensor-core GEMM v9 (fused rope+rms epilogues); final-wait fixed.
// ---------------------------------------------------------------------------
constexpr int BM = 128, BN = 128;
constexpr int APADW = 20;
constexpr int BPADW = 136;
constexpr int ABYTES = BM * APADW * 4;
constexpr int BBYTES = 16 * BPADW * 4;
constexpr int STAGEB = ABYTES + BBYTES;
constexpr int GEMM_SMEM9 = 3 * STAGEB;  // 56832

__global__ __launch_bounds__(128) void hgemm_v9(
    const __half* __restrict__ A0, const __half* __restrict__ A1,
    const __half* __restrict__ A2, const uint32_t* __restrict__ WW,
    int wbase, float* __restrict__ CF2, float* __restrict__ CFo,
    __half* __restrict__ qsd, __half* __restrict__ khd,
    const __nv_bfloat16* __restrict__ ct, const __nv_bfloat16* __restrict__ st,
    int M, int N, int K) {
    extern __shared__ char smem[];
    const uint32_t sb = smem_u32(smem);

    const int z = blockIdx.z;
    const __half* A = (z == 0) ? A0 : (z == 1) ? A1 : A2;
    const uint32_t* Wp = WW + (size_t)(wbase + z) * (CD / 2) * CD;
    const int emode = (wbase == 0) ? z : 3;

    const int t    = threadIdx.x;
    const int lane = t & 31;
    const int warp = t >> 5;
    const int wm   = warp & 1;
    const int wn   = warp >> 1;
    const int gid  = lane >> 2;
    const int tg   = lane & 3;

    const int m0b = blockIdx.y * BM;
    const int n0b = blockIdx.x * BN;

    const int NC = K / 32;

    float c[4][8][4];
#pragma unroll
    for (int mt = 0; mt < 4; ++mt)
#pragma unroll
        for (int nt = 0; nt < 8; ++nt)
#pragma unroll
            for (int i = 0; i < 4; ++i) c[mt][nt][i] = 0.f;

    auto issue = [&](int ck, int s) {
        const int kn = ck * 32;
        const uint32_t abase = sb + s * STAGEB;
        const uint32_t bbase = abase + ABYTES;
#pragma unroll
        for (int i = 0; i < 4; ++i) {
            const int ci = t + i * 128;
            const int ar = ci >> 2, as = ci & 3;
            cp16(abase + ar * (APADW * 4) + as * 16,
                 &A[(size_t)(m0b + ar) * K + kn + as * 8]);
            const int br = ci >> 5, bs = ci & 31;
            cp16(bbase + (br * BPADW + bs * 4) * 4,
                 &Wp[(size_t)(kn / 2 + br) * N + n0b + bs * 4]);
        }
        CP_COMMIT();
    };

    issue(0, 0);
    issue(1, 1);

    for (int ck = 0; ck < NC; ++ck) {
        if (ck + 1 < NC) CP_WAIT1(); else CP_WAIT0();
        __syncthreads();
        if (ck + 2 < NC) issue(ck + 2, (ck + 2) % 3);

        const int s = ck % 3;
        const uint32_t* As = (const uint32_t*)(smem + s * STAGEB);
        const uint32_t* Bs = (const uint32_t*)(smem + s * STAGEB + ABYTES);

#pragma unroll
        for (int ks = 0; ks < 2; ++ks) {
            uint32_t af[4][4], bf[8][2];
#pragma unroll
            for (int mt = 0; mt < 4; ++mt) {
                const int mm = wm * 64 + mt * 16 + gid;
                af[mt][0] = As[mm * APADW + ks * 8 + tg];
                af[mt][1] = As[(mm + 8) * APADW + ks * 8 + tg];
                af[mt][2] = As[mm * APADW + ks * 8 + tg + 4];
                af[mt][3] = As[(mm + 8) * APADW + ks * 8 + tg + 4];
            }
#pragma unroll
            for (int nt = 0; nt < 8; ++nt) {
                const int nn = wn * 64 + nt * 8 + gid;
                bf[nt][0] = Bs[(ks * 8 + tg) * BPADW + nn];
                bf[nt][1] = Bs[(ks * 8 + tg + 4) * BPADW + nn];
            }
#pragma unroll
            for (int mt = 0; mt < 4; ++mt)
#pragma unroll
                for (int nt = 0; nt < 8; ++nt)
                    mma_f16(c[mt][nt], af[mt], bf[nt][0], bf[nt][1]);
        }
    }

    if (emode >= 2) {
        float* C = (emode == 2) ? CF2 : CFo;
#pragma unroll
        for (int mt = 0; mt < 4; ++mt) {
            const int r0 = m0b + wm * 64 + mt * 16 + gid;
#pragma unroll
            for (int nt = 0; nt < 8; ++nt) {
                const int cc = n0b + wn * 64 + nt * 8 + tg * 2;
                *(float2*)&C[(size_t)r0 * N + cc]       = make_float2(c[mt][nt][0], c[mt][nt][1]);
                *(float2*)&C[(size_t)(r0 + 8) * N + cc] = make_float2(c[mt][nt][2], c[mt][nt][3]);
            }
        }
    } else {
        const float scale =
            (emode == 0) ? (0.125f * 1.4426950408889634f) : 1.0f;
        __half* dst = (emode == 0) ? qsd : khd;
        const int head = blockIdx.x * 2 + wn;
#pragma unroll
        for (int mt = 0; mt < 4; ++mt) {
#pragma unroll
            for (int hf = 0; hf < 2; ++hf) {
                const int row = m0b + wm * 64 + mt * 16 + gid + hf * 8;
                const int sp  = row & (CS - 1);
                float y1[8], y2[8];
                float ss = 0.f;
#pragma unroll
                for (int nt = 0; nt < 4; ++nt) {
                    const int d = nt * 8 + tg * 2;
                    const uint32_t cw = *(const uint32_t*)&ct[sp * 32 + d];
                    const uint32_t sw = *(const uint32_t*)&st[sp * 32 + d];
                    const __nv_bfloat162 cb = *(const __nv_bfloat162*)&cw;
                    const __nv_bfloat162 sb2 = *(const __nv_bfloat162*)&sw;
                    const float c0 = __bfloat162float(cb.x);
                    const float c1 = __bfloat162float(cb.y);
                    const float s0 = __bfloat162float(sb2.x);
                    const float s1 = __bfloat162float(sb2.y);
                    const float x1a = c[mt][nt][hf * 2 + 0];
                    const float x1b = c[mt][nt][hf * 2 + 1];
                    const float x2a = c[mt][nt + 4][hf * 2 + 0];
                    const float x2b = c[mt][nt + 4][hf * 2 + 1];
                    y1[2 * nt + 0] = x1a * c0 + x2a * s0;
                    y2[2 * nt + 0] = -x1a * s0 + x2a * c0;
                    y1[2 * nt + 1] = x1b * c1 + x2b * s1;
                    y2[2 * nt + 1] = -x1b * s1 + x2b * c1;
                    ss += y1[2 * nt] * y1[2 * nt] + y2[2 * nt] * y2[2 * nt] +
                          y1[2 * nt + 1] * y1[2 * nt + 1] +
                          y2[2 * nt + 1] * y2[2 * nt + 1];
                }
                ss += __shfl_xor_sync(0xffffffffu, ss, 1);
                ss += __shfl_xor_sync(0xffffffffu, ss, 2);
                const float rms = sqrtf(ss * (1.0f / 64.0f) + 1e-9f);
                const float ir  = scale / rms;
                const size_t ob = (size_t)row * CD + head * CHD;
#pragma unroll
                for (int nt = 0; nt < 4; ++nt) {
                    const int d = nt * 8 + tg * 2;
                    *(uint32_t*)&dst[ob + d] =
                        packh2(y1[2 * nt] * ir, y1[2 * nt + 1] * ir);
                    *(uint32_t*)&dst[ob + d + 32] =
                        packh2(y2[2 * nt] * ir, y2[2 * nt + 1] * ir);
                }
            }
        }
    }
}

// ---------------------------------------------------------------------------
// Causal flash attention, fp16 m16n8k16, no online max (|logit|<=8 bound),
// async KV fill (cp.async, 3 stages), ldmatrix.x4 for ALL b-fragments.
// K smem: [32 kv][36 pair-words]; V smem d-major: [64 d][20 pair-words].
// ---------------------------------------------------------------------------
__global__ __launch_bounds__(256, 2) void flash_attn_f16(
    const __half* __restrict__ qs, const __half* __restrict__ kh,
    const uint32_t* __restrict__ vt, __half* __restrict__ o) {
    __shared__ uint32_t Kw[3][32][36];
    __shared__ uint32_t Vt[3][64][20];

    const int t    = threadIdx.x;
    const int lane = t & 31;
    const int warp = t >> 5;
    const int gid  = lane >> 2;
    const int tg   = lane & 3;

    const int q0 = (gridDim.x - 1 - blockIdx.x) * 128;
    const int bh = blockIdx.y;
    const int b = bh >> 4, h = bh & 15;
    const size_t base = ((size_t)b * CS * CH + h) * CHD;
    const size_t vtb  = (size_t)bh * 64 * (CS / 2);
    const int rs = CH * CHD;

    const int qrow0 = q0 + warp * 16 + gid;
    const int qrow1 = qrow0 + 8;

    // fill mappings
    const int kr_ = t >> 3;        // K row 0..31
    const int kw_ = (t & 7) * 4;   // K word seg
    const int vd_ = t >> 2;        // V d-row 0..63
    const int vsg = (t & 3) * 4;   // V word seg

    // ldmatrix lane constants
    const int mi = lane >> 3, r8 = lane & 7;
    const uint32_t kconst = (uint32_t)(((mi >> 1) * 8 + r8) * 144 + (mi & 1) * 16);
    const uint32_t vconst = (uint32_t)(((mi >> 1) * 8 + r8) * 80 + (mi & 1) * 16);
    const uint32_t ksb = smem_u32(&Kw[0][0][0]);
    const uint32_t vsb = smem_u32(&Vt[0][0][0]);

    // Q a-fragments (scale pre-folded in rope epilogue)
    uint32_t qa[4][4];
#pragma unroll
    for (int ks = 0; ks < 4; ++ks) {
        qa[ks][0] = *(const uint32_t*)&qs[base + (size_t)qrow0 * rs + ks * 16 + 2 * tg];
        qa[ks][1] = *(const uint32_t*)&qs[base + (size_t)qrow1 * rs + ks * 16 + 2 * tg];
        qa[ks][2] = *(const uint32_t*)&qs[base + (size_t)qrow0 * rs + ks * 16 + 8 + 2 * tg];
        qa[ks][3] = *(const uint32_t*)&qs[base + (size_t)qrow1 * rs + ks * 16 + 8 + 2 * tg];
    }

    float oa[8][4];
#pragma unroll
    for (int dt = 0; dt < 8; ++dt)
#pragma unroll
        for (int i = 0; i < 4; ++i) oa[dt][i] = 0.f;

    float l0 = 0.f, l1 = 0.f;

    auto issue = [&](int kt, int s) {
        const int kv0 = kt << 5;
        cp16(ksb + s * 4608 + kr_ * 144 + kw_ * 4,
             &kh[base + (size_t)(kv0 + kr_) * rs + kw_ * 2]);
        cp16(vsb + s * 5120 + vd_ * 80 + vsg * 4,
             &vt[vtb + (size_t)vd_ * (CS / 2) + (kv0 >> 1) + vsg]);
        CP_COMMIT();
    };

    const int nkt = (q0 >> 5) + 4;
    issue(0, 0);
    if (nkt > 1) issue(1, 1);

    for (int kt = 0; kt < nkt; ++kt) {
        if (kt + 1 < nkt) CP_WAIT1(); else CP_WAIT0();
        __syncthreads();
        if (kt + 2 < nkt) issue(kt + 2, (kt + 2) % 3);

        const int s = kt % 3;
        const int kv0 = kt << 5;
        const uint32_t kbase = ksb + s * 4608 + kconst;
        const uint32_t vbase = vsb + s * 5120 + vconst;

        // ---- scores (log2 domain), K b-frags via ldmatrix.x4 ----
        float sc[4][4];
#pragma unroll
        for (int nt = 0; nt < 4; ++nt)
#pragma unroll
            for (int i = 0; i < 4; ++i) sc[nt][i] = 0.f;

#pragma unroll
        for (int ks = 0; ks < 4; ++ks) {
#pragma unroll
            for (int c2 = 0; c2 < 2; ++c2) {
                uint32_t r0, r1, r2, r3;
                ldsm4(r0, r1, r2, r3, kbase + c2 * 2304 + ks * 32);
                mma_f16(sc[2 * c2],     qa[ks], r0, r1);
                mma_f16(sc[2 * c2 + 1], qa[ks], r2, r3);
            }
        }

        // ---- causal mask ----
        const bool needmask = (kv0 + 31 > qrow0);
        if (needmask) {
#pragma unroll
            for (int nt = 0; nt < 4; ++nt) {
                const int c0 = kv0 + nt * 8 + 2 * tg;
                const int c1 = c0 + 1;
                if (c0 > qrow0) sc[nt][0] = -1e9f;
                if (c1 > qrow0) sc[nt][1] = -1e9f;
                if (c0 > qrow1) sc[nt][2] = -1e9f;
                if (c1 > qrow1) sc[nt][3] = -1e9f;
            }
        }

        // ---- p = exp2(sc); accumulate row sums ----
        float pf[4][4];
        float s0 = 0.f, s1 = 0.f;
#pragma unroll
        for (int nt = 0; nt < 4; ++nt) {
            pf[nt][0] = ex2(sc[nt][0]);
            pf[nt][1] = ex2(sc[nt][1]);
            pf[nt][2] = ex2(sc[nt][2]);
            pf[nt][3] = ex2(sc[nt][3]);
            s0 += pf[nt][0] + pf[nt][1];
            s1 += pf[nt][2] + pf[nt][3];
        }
        l0 += s0;
        l1 += s1;

        // ---- P a-fragments: direct pack (fp16 FA identity) ----
        uint32_t pa[2][4];
#pragma unroll
        for (int hh = 0; hh < 2; ++hh) {
            pa[hh][0] = packh2(pf[2 * hh][0], pf[2 * hh][1]);
            pa[hh][1] = packh2(pf[2 * hh][2], pf[2 * hh][3]);
            pa[hh][2] = packh2(pf[2 * hh + 1][0], pf[2 * hh + 1][1]);
            pa[hh][3] = packh2(pf[2 * hh + 1][2], pf[2 * hh + 1][3]);
        }

        // ---- PV, V b-frags via ldmatrix.x4 from d-major Vt ----
#pragma unroll
        for (int ks2 = 0; ks2 < 2; ++ks2) {
#pragma unroll
            for (int j = 0; j < 4; ++j) {
                uint32_t r0, r1, r2, r3;
                ldsm4(r0, r1, r2, r3, vbase + j * 1280 + ks2 * 32);
                mma_f16(oa[2 * j],     pa[ks2], r0, r1);
                mma_f16(oa[2 * j + 1], pa[ks2], r2, r3);
            }
        }
    }

    // ---- row-sum reduction + normalize + fp16 store ----
    l0 += __shfl_xor_sync(0xffffffffu, l0, 1);
    l0 += __shfl_xor_sync(0xffffffffu, l0, 2);
    l1 += __shfl_xor_sync(0xffffffffu, l1, 1);
    l1 += __shfl_xor_sync(0xffffffffu, l1, 2);
    const float il0 = 1.0f / l0;
    const float il1 = 1.0f / l1;
#pragma unroll
    for (int dt = 0; dt < 8; ++dt) {
        const int cc = dt * 8 + 2 * tg;
        *(uint32_t*)&o[base + (size_t)qrow0 * rs + cc] =
            packh2(oa[dt][0] * il0, oa[dt][1] * il0);
        *(uint32_t*)&o[base + (size_t)qrow1 * rs + cc] =
            packh2(oa[dt][2] * il1, oa[dt][3] * il1);
    }
}

// ---------------------------------------------------------------------------
// Launch
// ---------------------------------------------------------------------------
extern "C" void kernel_launch(void* const* d_in, const int* in_sizes, int n_in,
                              void* d_out, int out_size) {
    (void)in_sizes; (void)n_in; (void)out_size;
    const float* Q  = (const float*)d_in[0];
    const float* K  = (const float*)d_in[1];
    const float* V  = (const float*)d_in[2];
    const float* Wq = (const float*)d_in[4];
    const float* Wk = (const float*)d_in[5];
    const float* Wv = (const float*)d_in[6];
    const float* Wo = (const float*)d_in[7];
    float* out = (float*)d_out;

    float* gv;
    __half *gvals_h, *qh, *kih, *vih, *kh, *qsh;
    uint32_t *ww, *vtp;
    __nv_bfloat16 *ct, *st;
    cudaGetSymbolAddress((void**)&gv, g_v);
    cudaGetSymbolAddress((void**)&gvals_h, g_vals_h);
    cudaGetSymbolAddress((void**)&qh, g_qh);
    cudaGetSymbolAddress((void**)&kih, g_kih);
    cudaGetSymbolAddress((void**)&vih, g_vih);
    cudaGetSymbolAddress((void**)&ww, g_ww);
    cudaGetSymbolAddress((void**)&kh, g_kh);
    cudaGetSymbolAddress((void**)&qsh, g_qs);
    cudaGetSymbolAddress((void**)&vtp, g_vt);
    cudaGetSymbolAddress((void**)&ct, g_ct);
    cudaGetSymbolAddress((void**)&st, g_st);

    cudaFuncSetAttribute(hgemm_v9, cudaFuncAttributeMaxDynamicSharedMemorySize,
                         GEMM_SMEM9);

    const int M = MT;  // 4096

    // 0) pre-convert inputs + weights to fp16; rope tables
    dim3 pgrid(MT * CD / 4 / 256, 7);
    prep_cvt<<<pgrid, 256>>>(Q, K, V, Wq, Wk, Wv, Wo, qh, kih, vih, ww);
    prep_tables<<<CS * 32 / 256, 256>>>(ct, st);

    // 1) QKV projections with fused rope+rms epilogues (q->qs, k->kh, v->gv)
    dim3 ggrid3(CD / BN, M / BM, 3);
    hgemm_v9<<<ggrid3, 128, GEMM_SMEM9>>>(qh, kih, vih, ww, 0, gv, nullptr,
                                          qsh, kh, ct, st, M, CD, CD);

    // 2) V d-major pair-pack (transpose)
    pack_vt<<<dim3(CS / 64, CB * CH), 256>>>(gv, vtp);

    // 3) attention (async fills + ldmatrix; writes fp16)
    dim3 agrid(CS / 128, CB * CH);
    flash_attn_f16<<<agrid, 256>>>(qsh, kh, vtp, gvals_h);

    // 4) output projection (plain fp32 epilogue)
    dim3 ggrid1(CD / BN, M / BM, 1);
    hgemm_v9<<<ggrid1, 128, GEMM_SMEM9>>>(gvals_h, nullptr, nullptr, ww, 3,
                                          nullptr, out, nullptr, nullptr, ct,
                                          st, M, CD, CD);
}